// round 8
// baseline (speedup 1.0000x reference)
#include <cuda_runtime.h>
#include <math.h>

// Problem constants
#define B_  2048
#define T_  512
#define F_  32
#define H_  128
#define BT  14        // batch rows per CTA -> 147 CTAs = one wave on 148 SMs
#define P_  7         // batch pairs per CTA (each thread handles all 7)
#define NT  512
#define CWHH 3        // Whh0 kg-rows cached in SMEM (of 8)
#define HSTR 136      // h pair-row stride (float2): 4 quarters * (32+2)
#define XSTR 40       // x pair-row stride (float2): 4 * (8+2)
#define QH   34       // h quarter stride (float2)
#define QX   10       // x quarter stride (float2)

typedef unsigned long long ull;

// Permuted weights: idx = ((kg*16 + w)*4 + gt)*32 + lane, lane = j_sub*4 + q.
// gate = gt*128 + 8w + j_sub ; k = q*(KD/4) + kg*4.  +2 pad rows for prefetch.
__device__ float4 g_Wih0p[2 * 2048];
__device__ float4 g_Whh0p[10 * 2048];
__device__ float4 g_Wih1p[10 * 2048];
__device__ float4 g_Whh1p[10 * 2048];

__global__ void prep(const float* __restrict__ Wih0,
                     const float* __restrict__ Whh0,
                     const float* __restrict__ Wih1,
                     const float* __restrict__ Whh1) {
    int idx = blockIdx.x * blockDim.x + threadIdx.x;  // 0..16383
    int lane = idx & 31, gt = (idx >> 5) & 3, w = (idx >> 7) & 15, kg = idx >> 11;
    int js = lane >> 2, q = lane & 3;
    int gate = gt * 128 + 8 * w + js;
    int k = q * 32 + kg * 4;
    g_Whh0p[idx] = *(const float4*)(Whh0 + gate * 128 + k);
    g_Wih1p[idx] = *(const float4*)(Wih1 + gate * 128 + k);
    g_Whh1p[idx] = *(const float4*)(Whh1 + gate * 128 + k);
    if (kg < 2) {
        int k2 = q * 8 + kg * 4;
        g_Wih0p[idx] = *(const float4*)(Wih0 + gate * 32 + k2);
    }
}

__device__ __forceinline__ ull ffma2(ull a, ull b, ull c) {
    ull d;
    asm("fma.rn.f32x2 %0, %1, %2, %3;" : "=l"(d) : "l"(a), "l"(b), "l"(c));
    return d;
}
__device__ __forceinline__ ull addx2(ull a, ull b) {
    ull r;
    asm("add.rn.f32x2 %0, %1, %2;" : "=l"(r) : "l"(a), "l"(b));
    return r;
}
__device__ __forceinline__ ull dup2(float w) {
    ull d;
    asm("mov.b64 %0, {%1, %1};" : "=l"(d) : "f"(w));
    return d;
}
__device__ __forceinline__ float2 u2f(ull v) {
    float2 r;
    asm("mov.b64 {%0, %1}, %2;" : "=f"(r.x), "=f"(r.y) : "l"(v));
    return r;
}
__device__ __forceinline__ float sigm(float x) {
    return 1.0f / (1.0f + __expf(-x));
}
__device__ __forceinline__ float tanh_f(float x) {
    float e = __expf(-2.0f * fabsf(x));
    float t = (1.0f - e) / (1.0f + e);
    return x >= 0.0f ? t : -t;
}

// One k-group: all 4 gates, all 7 pairs. hq already includes quarter offset.
__device__ __forceinline__ void kbody4(const float4 wv[4],
                                       const float2* __restrict__ hq,
                                       const int pstride,
                                       ull z[4][P_], const int kidx) {
    ull d[4][4];
#pragma unroll
    for (int gt = 0; gt < 4; ++gt) {
        d[gt][0] = dup2(wv[gt].x); d[gt][1] = dup2(wv[gt].y);
        d[gt][2] = dup2(wv[gt].z); d[gt][3] = dup2(wv[gt].w);
    }
#pragma unroll
    for (int p = 0; p < P_; ++p) {
        const ulonglong2* hv = (const ulonglong2*)(hq + p * pstride + kidx * 4);
        ulonglong2 v0 = hv[0], v1 = hv[1];
#pragma unroll
        for (int gt = 0; gt < 4; ++gt) {
            ull zz = z[gt][p];
            zz = ffma2(v0.x, d[gt][0], zz);
            zz = ffma2(v0.y, d[gt][1], zz);
            zz = ffma2(v1.x, d[gt][2], zz);
            zz = ffma2(v1.y, d[gt][3], zz);
            z[gt][p] = zz;
        }
    }
}

// Panel from SMEM weight cache.
template <int KG>
__device__ __forceinline__ void panel_s(const float4* __restrict__ Ws,
                                        const float2* __restrict__ hq,
                                        const int pstride, const int kbase,
                                        ull z[4][P_]) {
#pragma unroll 1
    for (int kg = 0; kg < KG; ++kg) {
        float4 wv[4];
#pragma unroll
        for (int gt = 0; gt < 4; ++gt) wv[gt] = Ws[kg * 2048 + gt * 32];
        kbody4(wv, hq, pstride, z, kbase + kg);
    }
}

// Panel streamed from global, distance-2 rolling prefetch (+2 pad rows exist).
template <int KG>
__device__ __forceinline__ void panel_g(const float4* __restrict__ Wt,
                                        const float2* __restrict__ hq,
                                        const int pstride, const int kbase,
                                        ull z[4][P_]) {
    float4 w0[4], w1[4];
#pragma unroll
    for (int gt = 0; gt < 4; ++gt) { w0[gt] = Wt[gt * 32]; w1[gt] = Wt[2048 + gt * 32]; }
#pragma unroll 1
    for (int kg = 0; kg < KG; ++kg) {
        float4 wn[4];
#pragma unroll
        for (int gt = 0; gt < 4; ++gt) wn[gt] = Wt[(size_t)(kg + 2) * 2048 + gt * 32];
        kbody4(w0, hq, pstride, z, kbase + kg);
#pragma unroll
        for (int gt = 0; gt < 4; ++gt) { w0[gt] = w1[gt]; w1[gt] = wn[gt]; }
    }
}

// Butterfly-sum partials across the 4 q-lanes (packed f32x2 adds).
__device__ __forceinline__ void reduce_q(ull z[4][P_]) {
#pragma unroll
    for (int gt = 0; gt < 4; ++gt)
#pragma unroll
        for (int p = 0; p < P_; ++p) {
            ull v = z[gt][p];
            v = addx2(v, __shfl_xor_sync(0xffffffffu, v, 1));
            v = addx2(v, __shfl_xor_sync(0xffffffffu, v, 2));
            z[gt][p] = v;
        }
}

// Gate math on all lanes (uniform); only q==0 stores c and h.
__device__ __forceinline__ void gate_store(ull z[4][P_],
                                           float2* __restrict__ ca,
                                           float2* __restrict__ hnext,
                                           const int j, const bool st) {
    const int jq = (j >> 5) * QH + (j & 31);
#pragma unroll
    for (int p = 0; p < P_; ++p) {
        float2 zi = u2f(z[0][p]), zf = u2f(z[1][p]);
        float2 zg = u2f(z[2][p]), zo = u2f(z[3][p]);
        float2 c = ca[p * H_ + j];
        float2 nc, nh;
        nc.x = sigm(zf.x) * c.x + sigm(zi.x) * tanh_f(zg.x);
        nc.y = sigm(zf.y) * c.y + sigm(zi.y) * tanh_f(zg.y);
        nh.x = sigm(zo.x) * tanh_f(nc.x);
        nh.y = sigm(zo.y) * tanh_f(nc.y);
        if (st) {
            ca[p * H_ + j] = nc;
            hnext[p * HSTR + jq] = nh;
        }
    }
}

extern __shared__ float4 smem4[];

__global__ void __launch_bounds__(NT, 1)
lstm_persistent(const float* __restrict__ x,
                const float* __restrict__ b0,
                const float* __restrict__ b1,
                const float* __restrict__ Wfc,
                const float* __restrict__ bfc,
                float* __restrict__ out) {
    // SMEM: [Wih0 cache 4096 f4][Whh0 cache CWHH*2048 f4][f2 region]
    float2* f2b = (float2*)(smem4 + 4096 + CWHH * 2048);
    // f2 offsets: h0 x2 @0, h1 x2 @1904, c0 @3808, c1 @4704, x x2 @5600
    const int F2TOT = 4 * P_ * HSTR + 2 * P_ * H_ + 2 * P_ * XSTR;  // 6160

    const int tid = threadIdx.x;
    const int w = tid >> 5, lane = tid & 31;
    const int js = lane >> 2, q = lane & 3;
    const int j = 8 * w + js;
    const bool st = (q == 0);
    const int b_base = blockIdx.x * BT;
    const int nb = min(BT, B_ - b_base);
    const int qh = q * QH, qx = q * QX;
    const int toff = w * 128 + lane;

    // fill weight caches (once per launch)
    for (int i = tid; i < 4096; i += NT) smem4[i] = g_Wih0p[i];
    for (int i = tid; i < CWHH * 2048; i += NT) smem4[4096 + i] = g_Whh0p[i];
    // zero h/c/x region (pads included)
    for (int i = tid; i < F2TOT; i += NT) f2b[i] = make_float2(0.f, 0.f);
    // stage x(t=0)
    for (int i = tid; i < BT * F_; i += NT) {
        int b = i / F_, f = i % F_;
        float v = (b < nb) ? x[((size_t)(b_base + b) * T_) * F_ + f] : 0.f;
        ((float*)(f2b + 5600))[((b >> 1) * XSTR + (f >> 3) * QX + (f & 7)) * 2 + (b & 1)] = v;
    }

    float bv0[4], bv1[4];
#pragma unroll
    for (int gt = 0; gt < 4; ++gt) {
        bv0[gt] = st ? b0[gt * H_ + j] : 0.f;
        bv1[gt] = st ? b1[gt * H_ + j] : 0.f;
    }

    __syncthreads();

    int cur = 0;
    for (int t = 0; t < T_; ++t) {
        float2* h0i = f2b + cur * (P_ * HSTR);
        float2* h0o = f2b + (cur ^ 1) * (P_ * HSTR);
        float2* h1i = f2b + 1904 + cur * (P_ * HSTR);
        float2* h1o = f2b + 1904 + (cur ^ 1) * (P_ * HSTR);
        float2* c0a = f2b + 3808;
        float2* c1a = f2b + 4704;
        float2* xi = f2b + 5600 + cur * (P_ * XSTR);
        float2* xo = f2b + 5600 + (cur ^ 1) * (P_ * XSTR);

        // ---------- layer 0 ----------
        ull z[4][P_];
#pragma unroll
        for (int gt = 0; gt < 4; ++gt) {
            ull bz = dup2(bv0[gt]);
#pragma unroll
            for (int p = 0; p < P_; ++p) z[gt][p] = bz;
        }
        panel_s<2>(smem4 + toff, xi + qx, XSTR, 0, z);
        panel_s<CWHH>(smem4 + 4096 + toff, h0i + qh, HSTR, 0, z);
        panel_g<8 - CWHH>(g_Whh0p + CWHH * 2048 + toff, h0i + qh, HSTR, CWHH, z);
        reduce_q(z);
        gate_store(z, c0a, h0o, j, st);

        // stage x(t+1)
        if (t + 1 < T_) {
            for (int i = tid; i < BT * F_; i += NT) {
                int b = i / F_, f = i % F_;
                float v = (b < nb)
                    ? x[((size_t)(b_base + b) * T_ + t + 1) * F_ + f] : 0.f;
                ((float*)xo)[((b >> 1) * XSTR + (f >> 3) * QX + (f & 7)) * 2 + (b & 1)] = v;
            }
        }
        __syncthreads();

        // ---------- layer 1 ----------
#pragma unroll
        for (int gt = 0; gt < 4; ++gt) {
            ull bz = dup2(bv1[gt]);
#pragma unroll
            for (int p = 0; p < P_; ++p) z[gt][p] = bz;
        }
        panel_g<8>(g_Wih1p + toff, h0o + qh, HSTR, 0, z);
        panel_g<8>(g_Whh1p + toff, h1i + qh, HSTR, 0, z);
        reduce_q(z);
        gate_store(z, c1a, h1o, j, st);
        __syncthreads();
        cur ^= 1;
    }

    // FC head: h1 final is in buffer 'cur'
    if (tid < nb) {
        const float2* hf = f2b + 1904 + cur * (P_ * HSTR) + (tid >> 1) * HSTR;
        float s = bfc[0];
        int sel = tid & 1;
#pragma unroll
        for (int k = 0; k < H_; ++k) {
            float2 hv = hf[(k >> 5) * QH + (k & 31)];
            s = fmaf(sel ? hv.y : hv.x, Wfc[k], s);
        }
        out[b_base + tid] = s;
    }
}

extern "C" void kernel_launch(void* const* d_in, const int* in_sizes, int n_in,
                              void* d_out, int out_size) {
    const float* x    = (const float*)d_in[0];
    const float* Wih0 = (const float*)d_in[1];
    const float* Whh0 = (const float*)d_in[2];
    const float* b0   = (const float*)d_in[3];
    const float* Wih1 = (const float*)d_in[4];
    const float* Whh1 = (const float*)d_in[5];
    const float* b1   = (const float*)d_in[6];
    const float* Wfc  = (const float*)d_in[7];
    const float* bfc  = (const float*)d_in[8];
    float* out = (float*)d_out;
    (void)in_sizes; (void)n_in; (void)out_size;

    prep<<<64, 256>>>(Wih0, Whh0, Wih1, Whh1);

    const int smem_bytes =
        (4096 + CWHH * 2048) * (int)sizeof(float4) +
        (4 * P_ * HSTR + 2 * P_ * H_ + 2 * P_ * XSTR) * (int)sizeof(float2);
    cudaFuncSetAttribute(lstm_persistent,
                         cudaFuncAttributeMaxDynamicSharedMemorySize,
                         smem_bytes);

    lstm_persistent<<<(B_ + BT - 1) / BT, NT, smem_bytes>>>(
        x, b0, b1, Wfc, bfc, out);
}

// round 9
// speedup vs baseline: 1.3347x; 1.3347x over previous
#include <cuda_runtime.h>
#include <math.h>

// Problem constants
#define B_  2048
#define T_  512
#define F_  32
#define H_  128
#define G_  512      // 4*H
#define BT  14       // batch rows per CTA -> 147 CTAs = one wave on 148 SMs
#define P_  7        // batch-row pairs per CTA (each thread handles all 7)
#define NT  768      // 3 k-splits of 256 threads
#define PST 9        // zbuf pair stride in ull
#define CWHH 1       // Whh0 kg-rows cached in SMEM

typedef unsigned long long ull;

// Weights as [kg][gate] float4: coalesced LDG.128 per gate per k-group.
// Padded +2 kg rows for the distance-2 prefetch.
__device__ float4 g_Wih0T4[(F_ / 4 + 2) * G_];
__device__ float4 g_Whh0T4[(H_ / 4 + 2) * G_];
__device__ float4 g_Wih1T4[(H_ / 4 + 2) * G_];
__device__ float4 g_Whh1T4[(H_ / 4 + 2) * G_];

__global__ void prep(const float* __restrict__ Wih0,
                     const float* __restrict__ Whh0,
                     const float* __restrict__ Wih1,
                     const float* __restrict__ Whh1) {
    int idx = blockIdx.x * blockDim.x + threadIdx.x;  // 0 .. 512*32-1
    int g = idx >> 5, kg = idx & 31;
    if (kg < F_ / 4)
        g_Wih0T4[kg * G_ + g] = *(const float4*)(Wih0 + g * F_ + 4 * kg);
    g_Whh0T4[kg * G_ + g] = *(const float4*)(Whh0 + g * H_ + 4 * kg);
    g_Wih1T4[kg * G_ + g] = *(const float4*)(Wih1 + g * H_ + 4 * kg);
    g_Whh1T4[kg * G_ + g] = *(const float4*)(Whh1 + g * H_ + 4 * kg);
}

__device__ __forceinline__ ull ffma2(ull a, ull b, ull c) {
    ull d;
    asm("fma.rn.f32x2 %0, %1, %2, %3;" : "=l"(d) : "l"(a), "l"(b), "l"(c));
    return d;
}
__device__ __forceinline__ ull dup2(float w) {
    ull d;
    asm("mov.b64 %0, {%1, %1};" : "=l"(d) : "f"(w));
    return d;
}
__device__ __forceinline__ ull pack2(float lo, float hi) {
    return (ull)__float_as_uint(lo) | ((ull)__float_as_uint(hi) << 32);
}
__device__ __forceinline__ float2 u2f(ull v) {
    float2 r;
    asm("mov.b64 {%0, %1}, %2;" : "=f"(r.x), "=f"(r.y) : "l"(v));
    return r;
}
__device__ __forceinline__ float sigm(float x) {
    return 1.0f / (1.0f + __expf(-x));
}
__device__ __forceinline__ float tanh_f(float x) {
    float e = __expf(-2.0f * fabsf(x));
    float t = (1.0f - e) / (1.0f + e);
    return x >= 0.0f ? t : -t;
}

// Inner k-group body: z[q][p] += hpair[p][4k..4k+3] * w{a,b}, kidx absolute.
template <int KDIM>
__device__ __forceinline__ void kbody(float4 wa, float4 wb,
                                      const float2* __restrict__ hp,
                                      ull z[2][P_], int kidx) {
    ull a0 = dup2(wa.x), a1 = dup2(wa.y), a2 = dup2(wa.z), a3 = dup2(wa.w);
    ull b0 = dup2(wb.x), b1 = dup2(wb.y), b2 = dup2(wb.z), b3 = dup2(wb.w);
#pragma unroll
    for (int p = 0; p < P_; ++p) {
        const ulonglong2* hv = (const ulonglong2*)(hp + p * KDIM) + 2 * kidx;
        ulonglong2 v0 = hv[0];
        ulonglong2 v1 = hv[1];
        ull z0 = z[0][p], z1 = z[1][p];
        z0 = ffma2(v0.x, a0, z0);
        z0 = ffma2(v0.y, a1, z0);
        z0 = ffma2(v1.x, a2, z0);
        z0 = ffma2(v1.y, a3, z0);
        z1 = ffma2(v0.x, b0, z1);
        z1 = ffma2(v0.y, b1, z1);
        z1 = ffma2(v1.x, b2, z1);
        z1 = ffma2(v1.y, b3, z1);
        z[0][p] = z0; z[1][p] = z1;
    }
}

// GEMM panel over KG k-groups starting at absolute kg index kbase.
// W4 already points at the kbase row. Distance-2 rolling prefetch.
template <int KDIM, int KG>
__device__ __forceinline__ void gemm_g(const float4* __restrict__ W4,
                                       const float2* __restrict__ hp,
                                       int kbase, ull z[2][P_], int g0) {
    const float4* pA = W4 + g0;
    const float4* pB = W4 + g0 + 256;
    float4 wa0 = pA[0], wa1 = pA[G_];
    float4 wb0 = pB[0], wb1 = pB[G_];
#pragma unroll 1
    for (int kg = 0; kg < KG; ++kg) {
        float4 na = pA[(size_t)(kg + 2) * G_];
        float4 nb = pB[(size_t)(kg + 2) * G_];
        kbody<KDIM>(wa0, wb0, hp, z, kbase + kg);
        wa0 = wa1; wa1 = na;
        wb0 = wb1; wb1 = nb;
    }
}

// GEMM panel from SMEM cache. Ws points at the kbase row of the cache.
template <int KDIM, int KG>
__device__ __forceinline__ void gemm_s(const float4* __restrict__ Ws,
                                       const float2* __restrict__ hp,
                                       int kbase, ull z[2][P_], int g0) {
#pragma unroll 1
    for (int kg = 0; kg < KG; ++kg) {
        float4 wa = Ws[kg * G_ + g0];
        float4 wb = Ws[kg * G_ + g0 + 256];
        kbody<KDIM>(wa, wb, hp, z, kbase + kg);
    }
}

extern __shared__ float4 smem4[];

__global__ void __launch_bounds__(NT, 1)
lstm_persistent(const float* __restrict__ x,
                const float* __restrict__ b0,
                const float* __restrict__ b1,
                const float* __restrict__ Wfc,
                const float* __restrict__ bfc,
                float* __restrict__ out) {
    // SMEM: [Wih0 cache 8 rows][Whh0 cache CWHH rows][h0,c0,h1,c1][zbuf x3][x x2]
    float4* sWih0 = smem4;                            // 8*G_
    float4* sWhh0 = smem4 + (F_ / 4) * G_;            // CWHH*G_
    float2* hbase = (float2*)(smem4 + (F_ / 4 + CWHH) * G_);
    float2* h0p = hbase;                 // P_*H_
    float2* c0p = h0p + P_ * H_;
    float2* h1p = c0p + P_ * H_;
    float2* c1p = h1p + P_ * H_;
    ull* zbu0 = (ull*)(c1p + P_ * H_);   // G_*PST per split
    ull* zbu1 = zbu0 + G_ * PST;
    ull* zbu2 = zbu1 + G_ * PST;
    float2* xb[2] = { (float2*)(zbu2 + G_ * PST),
                      (float2*)(zbu2 + G_ * PST) + P_ * F_ };

    const int tid = threadIdx.x;
    const int g0 = tid & 255;            // gates g0 and g0+256
    const int sp = tid >> 8;             // k-split 0/1/2
    const int b_base = blockIdx.x * BT;
    const int nb = min(BT, B_ - b_base);
    ull* zmy = (sp == 0) ? zbu0 : (sp == 1) ? zbu1 : zbu2;

    // fill weight caches (once per launch)
    for (int i = tid; i < (F_ / 4) * G_; i += NT) sWih0[i] = g_Wih0T4[i];
    for (int i = tid; i < CWHH * G_; i += NT) sWhh0[i] = g_Whh0T4[i];
    // zero h/c
    for (int i = tid; i < 4 * P_ * H_; i += NT) hbase[i] = make_float2(0.f, 0.f);
    // stage x(t=0)
    for (int i = tid; i < BT * F_; i += NT) {
        int b = i / F_, f = i % F_;
        float v = (b < nb) ? x[((size_t)(b_base + b) * T_) * F_ + f] : 0.0f;
        ((float*)xb[0])[(b >> 1) * F_ * 2 + f * 2 + (b & 1)] = v;
    }

    // biases only in split 0's partial
    const ull bias0a = sp ? 0ull : pack2(b0[g0], b0[g0]);
    const ull bias0b = sp ? 0ull : pack2(b0[g0 + 256], b0[g0 + 256]);
    const ull bias1a = sp ? 0ull : pack2(b1[g0], b1[g0]);
    const ull bias1b = sp ? 0ull : pack2(b1[g0 + 256], b1[g0 + 256]);
    __syncthreads();

    int cur = 0;
    for (int t = 0; t < T_; ++t) {
        // ---------- layer 0 GEMM (3-way split-K) ----------
        ull z[2][P_];
#pragma unroll
        for (int p = 0; p < P_; ++p) { z[0][p] = bias0a; z[1][p] = bias0b; }
        if (sp == 0) {
            gemm_s<F_, 3>(sWih0, xb[cur], 0, z, g0);                  // x kg 0-2
            gemm_s<H_, CWHH>(sWhh0, h0p, 0, z, g0);                    // hh kg 0
            gemm_g<H_, 11 - CWHH>(g_Whh0T4 + CWHH * G_, h0p, CWHH, z, g0); // 1-10
        } else if (sp == 1) {
            gemm_s<F_, 3>(sWih0 + 3 * G_, xb[cur], 3, z, g0);          // x kg 3-5
            gemm_g<H_, 11>(g_Whh0T4 + 11 * G_, h0p, 11, z, g0);        // hh 11-21
        } else {
            gemm_s<F_, 2>(sWih0 + 6 * G_, xb[cur], 6, z, g0);          // x kg 6-7
            gemm_g<H_, 10>(g_Whh0T4 + 22 * G_, h0p, 22, z, g0);        // hh 22-31
        }
#pragma unroll
        for (int p = 0; p < P_; ++p) {
            zmy[g0 * PST + p] = z[0][p];
            zmy[(g0 + 256) * PST + p] = z[1][p];
        }
        __syncthreads();

        // ---------- layer 0 gate update (sums 3 partials) ----------
        for (int i = tid; i < P_ * H_; i += NT) {
            int p = i >> 7, j = i & (H_ - 1);
            float zix, ziy, zfx, zfy, zgx, zgy, zox, zoy;
            {
                float2 a0 = u2f(zbu0[(j      ) * PST + p]);
                float2 a1 = u2f(zbu1[(j      ) * PST + p]);
                float2 a2 = u2f(zbu2[(j      ) * PST + p]);
                zix = a0.x + a1.x + a2.x; ziy = a0.y + a1.y + a2.y;
            }
            {
                float2 a0 = u2f(zbu0[(j + 128) * PST + p]);
                float2 a1 = u2f(zbu1[(j + 128) * PST + p]);
                float2 a2 = u2f(zbu2[(j + 128) * PST + p]);
                zfx = a0.x + a1.x + a2.x; zfy = a0.y + a1.y + a2.y;
            }
            {
                float2 a0 = u2f(zbu0[(j + 256) * PST + p]);
                float2 a1 = u2f(zbu1[(j + 256) * PST + p]);
                float2 a2 = u2f(zbu2[(j + 256) * PST + p]);
                zgx = a0.x + a1.x + a2.x; zgy = a0.y + a1.y + a2.y;
            }
            {
                float2 a0 = u2f(zbu0[(j + 384) * PST + p]);
                float2 a1 = u2f(zbu1[(j + 384) * PST + p]);
                float2 a2 = u2f(zbu2[(j + 384) * PST + p]);
                zox = a0.x + a1.x + a2.x; zoy = a0.y + a1.y + a2.y;
            }
            float2 c = c0p[p * H_ + j];
            float2 nc, nh;
            nc.x = sigm(zfx) * c.x + sigm(zix) * tanh_f(zgx);
            nc.y = sigm(zfy) * c.y + sigm(ziy) * tanh_f(zgy);
            nh.x = sigm(zox) * tanh_f(nc.x);
            nh.y = sigm(zoy) * tanh_f(nc.y);
            c0p[p * H_ + j] = nc;
            h0p[p * H_ + j] = nh;
        }
        __syncthreads();

        // ---------- layer 1 GEMM (3-way split-K) ----------
#pragma unroll
        for (int p = 0; p < P_; ++p) { z[0][p] = bias1a; z[1][p] = bias1b; }
        if (sp == 0) {
            gemm_g<H_, 11>(g_Wih1T4, h0p, 0, z, g0);
            gemm_g<H_, 11>(g_Whh1T4, h1p, 0, z, g0);
        } else if (sp == 1) {
            gemm_g<H_, 11>(g_Wih1T4 + 11 * G_, h0p, 11, z, g0);
            gemm_g<H_, 11>(g_Whh1T4 + 11 * G_, h1p, 11, z, g0);
        } else {
            gemm_g<H_, 10>(g_Wih1T4 + 22 * G_, h0p, 22, z, g0);
            gemm_g<H_, 10>(g_Whh1T4 + 22 * G_, h1p, 22, z, g0);
        }
#pragma unroll
        for (int p = 0; p < P_; ++p) {
            zmy[g0 * PST + p] = z[0][p];
            zmy[(g0 + 256) * PST + p] = z[1][p];
        }
        // stage x(t+1) into the other buffer while z settles
        if (t + 1 < T_) {
            for (int i = tid; i < BT * F_; i += NT) {
                int b = i / F_, f = i % F_;
                float v = (b < nb)
                    ? x[((size_t)(b_base + b) * T_ + (t + 1)) * F_ + f]
                    : 0.0f;
                ((float*)xb[cur ^ 1])[(b >> 1) * F_ * 2 + f * 2 + (b & 1)] = v;
            }
        }
        __syncthreads();

        // ---------- layer 1 gate update ----------
        for (int i = tid; i < P_ * H_; i += NT) {
            int p = i >> 7, j = i & (H_ - 1);
            float zix, ziy, zfx, zfy, zgx, zgy, zox, zoy;
            {
                float2 a0 = u2f(zbu0[(j      ) * PST + p]);
                float2 a1 = u2f(zbu1[(j      ) * PST + p]);
                float2 a2 = u2f(zbu2[(j      ) * PST + p]);
                zix = a0.x + a1.x + a2.x; ziy = a0.y + a1.y + a2.y;
            }
            {
                float2 a0 = u2f(zbu0[(j + 128) * PST + p]);
                float2 a1 = u2f(zbu1[(j + 128) * PST + p]);
                float2 a2 = u2f(zbu2[(j + 128) * PST + p]);
                zfx = a0.x + a1.x + a2.x; zfy = a0.y + a1.y + a2.y;
            }
            {
                float2 a0 = u2f(zbu0[(j + 256) * PST + p]);
                float2 a1 = u2f(zbu1[(j + 256) * PST + p]);
                float2 a2 = u2f(zbu2[(j + 256) * PST + p]);
                zgx = a0.x + a1.x + a2.x; zgy = a0.y + a1.y + a2.y;
            }
            {
                float2 a0 = u2f(zbu0[(j + 384) * PST + p]);
                float2 a1 = u2f(zbu1[(j + 384) * PST + p]);
                float2 a2 = u2f(zbu2[(j + 384) * PST + p]);
                zox = a0.x + a1.x + a2.x; zoy = a0.y + a1.y + a2.y;
            }
            float2 c = c1p[p * H_ + j];
            float2 nc, nh;
            nc.x = sigm(zfx) * c.x + sigm(zix) * tanh_f(zgx);
            nc.y = sigm(zfy) * c.y + sigm(ziy) * tanh_f(zgy);
            nh.x = sigm(zox) * tanh_f(nc.x);
            nh.y = sigm(zoy) * tanh_f(nc.y);
            c1p[p * H_ + j] = nc;
            h1p[p * H_ + j] = nh;
        }
        __syncthreads();
        cur ^= 1;
    }

    // FC head
    if (tid < nb) {
        float s = bfc[0];
#pragma unroll
        for (int k = 0; k < H_; ++k) {
            float2 hv = h1p[(tid >> 1) * H_ + k];
            float h = (tid & 1) ? hv.y : hv.x;
            s = fmaf(h, Wfc[k], s);
        }
        out[b_base + tid] = s;
    }
}

extern "C" void kernel_launch(void* const* d_in, const int* in_sizes, int n_in,
                              void* d_out, int out_size) {
    const float* x    = (const float*)d_in[0];
    const float* Wih0 = (const float*)d_in[1];
    const float* Whh0 = (const float*)d_in[2];
    const float* b0   = (const float*)d_in[3];
    const float* Wih1 = (const float*)d_in[4];
    const float* Whh1 = (const float*)d_in[5];
    const float* b1   = (const float*)d_in[6];
    const float* Wfc  = (const float*)d_in[7];
    const float* bfc  = (const float*)d_in[8];
    float* out = (float*)d_out;
    (void)in_sizes; (void)n_in; (void)out_size;

    prep<<<(G_ * (H_ / 4)) / 256, 256>>>(Wih0, Whh0, Wih1, Whh1);

    const int smem_bytes =
        (F_ / 4 + CWHH) * G_ * (int)sizeof(float4) +   // weight caches
        4 * P_ * H_ * (int)sizeof(float2) +            // h/c
        3 * G_ * PST * (int)sizeof(ull) +              // split-K zbufs
        2 * P_ * F_ * (int)sizeof(float2);             // x double buffer
    cudaFuncSetAttribute(lstm_persistent,
                         cudaFuncAttributeMaxDynamicSharedMemorySize,
                         smem_bytes);

    lstm_persistent<<<(B_ + BT - 1) / BT, NT, smem_bytes>>>(
        x, b0, b1, Wfc, bfc, out);
}

// round 10
// speedup vs baseline: 1.3382x; 1.0026x over previous
#include <cuda_runtime.h>
#include <math.h>

// Problem constants
#define B_  2048
#define T_  512
#define F_  32
#define H_  128
#define G_  512      // 4*H
#define BT  14       // batch rows per CTA -> 147 CTAs = one wave on 148 SMs
#define P_  7        // batch-row pairs per CTA (each thread handles all 7)
#define NT  768      // 3 k-splits of 256 threads
#define PST 9        // zbuf pair stride in ull
#define CWHH 1       // Whh0 kg-rows cached in SMEM

typedef unsigned long long ull;

// Weights as [kg][gate] float4: coalesced LDG.128 per gate per k-group.
// Padded +2 kg rows for the distance-2 prefetch.
__device__ float4 g_Wih0T4[(F_ / 4 + 2) * G_];
__device__ float4 g_Whh0T4[(H_ / 4 + 2) * G_];
__device__ float4 g_Wih1T4[(H_ / 4 + 2) * G_];
__device__ float4 g_Whh1T4[(H_ / 4 + 2) * G_];

__global__ void prep(const float* __restrict__ Wih0,
                     const float* __restrict__ Whh0,
                     const float* __restrict__ Wih1,
                     const float* __restrict__ Whh1) {
    int idx = blockIdx.x * blockDim.x + threadIdx.x;  // 0 .. 512*32-1
    int g = idx >> 5, kg = idx & 31;
    if (kg < F_ / 4)
        g_Wih0T4[kg * G_ + g] = *(const float4*)(Wih0 + g * F_ + 4 * kg);
    g_Whh0T4[kg * G_ + g] = *(const float4*)(Whh0 + g * H_ + 4 * kg);
    g_Wih1T4[kg * G_ + g] = *(const float4*)(Wih1 + g * H_ + 4 * kg);
    g_Whh1T4[kg * G_ + g] = *(const float4*)(Whh1 + g * H_ + 4 * kg);
}

__device__ __forceinline__ ull ffma2(ull a, ull b, ull c) {
    ull d;
    asm("fma.rn.f32x2 %0, %1, %2, %3;" : "=l"(d) : "l"(a), "l"(b), "l"(c));
    return d;
}
__device__ __forceinline__ ull dup2(float w) {
    ull d;
    asm("mov.b64 %0, {%1, %1};" : "=l"(d) : "f"(w));
    return d;
}
__device__ __forceinline__ ull pack2(float lo, float hi) {
    return (ull)__float_as_uint(lo) | ((ull)__float_as_uint(hi) << 32);
}
__device__ __forceinline__ float2 u2f(ull v) {
    float2 r;
    asm("mov.b64 {%0, %1}, %2;" : "=f"(r.x), "=f"(r.y) : "l"(v));
    return r;
}
__device__ __forceinline__ float sigm(float x) {
    return 1.0f / (1.0f + __expf(-x));
}
__device__ __forceinline__ float tanh_f(float x) {
    float e = __expf(-2.0f * fabsf(x));
    float t = (1.0f - e) / (1.0f + e);
    return x >= 0.0f ? t : -t;
}

// Inner k-group body: z[q][p] += hpair[p][4k..4k+3] * w{a,b}, kidx absolute.
template <int KDIM>
__device__ __forceinline__ void kbody(float4 wa, float4 wb,
                                      const float2* __restrict__ hp,
                                      ull z[2][P_], int kidx) {
    ull a0 = dup2(wa.x), a1 = dup2(wa.y), a2 = dup2(wa.z), a3 = dup2(wa.w);
    ull b0 = dup2(wb.x), b1 = dup2(wb.y), b2 = dup2(wb.z), b3 = dup2(wb.w);
#pragma unroll
    for (int p = 0; p < P_; ++p) {
        const ulonglong2* hv = (const ulonglong2*)(hp + p * KDIM) + 2 * kidx;
        ulonglong2 v0 = hv[0];
        ulonglong2 v1 = hv[1];
        ull z0 = z[0][p], z1 = z[1][p];
        z0 = ffma2(v0.x, a0, z0);
        z0 = ffma2(v0.y, a1, z0);
        z0 = ffma2(v1.x, a2, z0);
        z0 = ffma2(v1.y, a3, z0);
        z1 = ffma2(v0.x, b0, z1);
        z1 = ffma2(v0.y, b1, z1);
        z1 = ffma2(v1.x, b2, z1);
        z1 = ffma2(v1.y, b3, z1);
        z[0][p] = z0; z[1][p] = z1;
    }
}

// GEMM panel over KG k-groups starting at absolute kg index kbase.
// W4 already points at the kbase row. Distance-2 rolling prefetch.
template <int KDIM, int KG>
__device__ __forceinline__ void gemm_g(const float4* __restrict__ W4,
                                       const float2* __restrict__ hp,
                                       int kbase, ull z[2][P_], int g0) {
    const float4* pA = W4 + g0;
    const float4* pB = W4 + g0 + 256;
    float4 wa0 = pA[0], wa1 = pA[G_];
    float4 wb0 = pB[0], wb1 = pB[G_];
#pragma unroll 1
    for (int kg = 0; kg < KG; ++kg) {
        float4 na = pA[(size_t)(kg + 2) * G_];
        float4 nb = pB[(size_t)(kg + 2) * G_];
        kbody<KDIM>(wa0, wb0, hp, z, kbase + kg);
        wa0 = wa1; wa1 = na;
        wb0 = wb1; wb1 = nb;
    }
}

// GEMM panel from SMEM cache. Ws points at the kbase row of the cache.
template <int KDIM, int KG>
__device__ __forceinline__ void gemm_s(const float4* __restrict__ Ws,
                                       const float2* __restrict__ hp,
                                       int kbase, ull z[2][P_], int g0) {
#pragma unroll 1
    for (int kg = 0; kg < KG; ++kg) {
        float4 wa = Ws[kg * G_ + g0];
        float4 wb = Ws[kg * G_ + g0 + 256];
        kbody<KDIM>(wa, wb, hp, z, kbase + kg);
    }
}

extern __shared__ float4 smem4[];

__global__ void __launch_bounds__(NT, 1)
lstm_persistent(const float* __restrict__ x,
                const float* __restrict__ b0,
                const float* __restrict__ b1,
                const float* __restrict__ Wfc,
                const float* __restrict__ bfc,
                float* __restrict__ out) {
    // SMEM: [Wih0 cache 8 rows][Whh0 cache CWHH rows][h0,c0,h1,c1][zbuf x3][x x2]
    float4* sWih0 = smem4;                            // 8*G_
    float4* sWhh0 = smem4 + (F_ / 4) * G_;            // CWHH*G_
    float2* hbase = (float2*)(smem4 + (F_ / 4 + CWHH) * G_);
    float2* h0p = hbase;                 // P_*H_
    float2* c0p = h0p + P_ * H_;
    float2* h1p = c0p + P_ * H_;
    float2* c1p = h1p + P_ * H_;
    ull* zbu0 = (ull*)(c1p + P_ * H_);   // G_*PST per split
    ull* zbu1 = zbu0 + G_ * PST;
    ull* zbu2 = zbu1 + G_ * PST;
    float2* xb[2] = { (float2*)(zbu2 + G_ * PST),
                      (float2*)(zbu2 + G_ * PST) + P_ * F_ };

    const int tid = threadIdx.x;
    const int g0 = tid & 255;            // gates g0 and g0+256
    const int sp = tid >> 8;             // k-split 0/1/2
    const int b_base = blockIdx.x * BT;
    const int nb = min(BT, B_ - b_base);
    ull* zmy = (sp == 0) ? zbu0 : (sp == 1) ? zbu1 : zbu2;

    // fill weight caches (once per launch)
    for (int i = tid; i < (F_ / 4) * G_; i += NT) sWih0[i] = g_Wih0T4[i];
    for (int i = tid; i < CWHH * G_; i += NT) sWhh0[i] = g_Whh0T4[i];
    // zero h/c
    for (int i = tid; i < 4 * P_ * H_; i += NT) hbase[i] = make_float2(0.f, 0.f);
    // stage x(t=0)
    for (int i = tid; i < BT * F_; i += NT) {
        int b = i / F_, f = i % F_;
        float v = (b < nb) ? x[((size_t)(b_base + b) * T_) * F_ + f] : 0.0f;
        ((float*)xb[0])[(b >> 1) * F_ * 2 + f * 2 + (b & 1)] = v;
    }

    // biases only in split 0's partial
    const ull bias0a = sp ? 0ull : pack2(b0[g0], b0[g0]);
    const ull bias0b = sp ? 0ull : pack2(b0[g0 + 256], b0[g0 + 256]);
    const ull bias1a = sp ? 0ull : pack2(b1[g0], b1[g0]);
    const ull bias1b = sp ? 0ull : pack2(b1[g0 + 256], b1[g0 + 256]);
    __syncthreads();

    int cur = 0;
    for (int t = 0; t < T_; ++t) {
        // ---------- layer 0 GEMM (3-way split-K) ----------
        ull z[2][P_];
#pragma unroll
        for (int p = 0; p < P_; ++p) { z[0][p] = bias0a; z[1][p] = bias0b; }
        if (sp == 0) {
            gemm_s<F_, 3>(sWih0, xb[cur], 0, z, g0);                  // x kg 0-2
            gemm_s<H_, CWHH>(sWhh0, h0p, 0, z, g0);                    // hh kg 0
            gemm_g<H_, 11 - CWHH>(g_Whh0T4 + CWHH * G_, h0p, CWHH, z, g0); // 1-10
        } else if (sp == 1) {
            gemm_s<F_, 3>(sWih0 + 3 * G_, xb[cur], 3, z, g0);          // x kg 3-5
            gemm_g<H_, 11>(g_Whh0T4 + 11 * G_, h0p, 11, z, g0);        // hh 11-21
        } else {
            gemm_s<F_, 2>(sWih0 + 6 * G_, xb[cur], 6, z, g0);          // x kg 6-7
            gemm_g<H_, 10>(g_Whh0T4 + 22 * G_, h0p, 22, z, g0);        // hh 22-31
        }
#pragma unroll
        for (int p = 0; p < P_; ++p) {
            zmy[g0 * PST + p] = z[0][p];
            zmy[(g0 + 256) * PST + p] = z[1][p];
        }
        __syncthreads();

        // ---------- layer 0 gate update (sums 3 partials) ----------
        for (int i = tid; i < P_ * H_; i += NT) {
            int p = i >> 7, j = i & (H_ - 1);
            float zix, ziy, zfx, zfy, zgx, zgy, zox, zoy;
            {
                float2 a0 = u2f(zbu0[(j      ) * PST + p]);
                float2 a1 = u2f(zbu1[(j      ) * PST + p]);
                float2 a2 = u2f(zbu2[(j      ) * PST + p]);
                zix = a0.x + a1.x + a2.x; ziy = a0.y + a1.y + a2.y;
            }
            {
                float2 a0 = u2f(zbu0[(j + 128) * PST + p]);
                float2 a1 = u2f(zbu1[(j + 128) * PST + p]);
                float2 a2 = u2f(zbu2[(j + 128) * PST + p]);
                zfx = a0.x + a1.x + a2.x; zfy = a0.y + a1.y + a2.y;
            }
            {
                float2 a0 = u2f(zbu0[(j + 256) * PST + p]);
                float2 a1 = u2f(zbu1[(j + 256) * PST + p]);
                float2 a2 = u2f(zbu2[(j + 256) * PST + p]);
                zgx = a0.x + a1.x + a2.x; zgy = a0.y + a1.y + a2.y;
            }
            {
                float2 a0 = u2f(zbu0[(j + 384) * PST + p]);
                float2 a1 = u2f(zbu1[(j + 384) * PST + p]);
                float2 a2 = u2f(zbu2[(j + 384) * PST + p]);
                zox = a0.x + a1.x + a2.x; zoy = a0.y + a1.y + a2.y;
            }
            float2 c = c0p[p * H_ + j];
            float2 nc, nh;
            nc.x = sigm(zfx) * c.x + sigm(zix) * tanh_f(zgx);
            nc.y = sigm(zfy) * c.y + sigm(ziy) * tanh_f(zgy);
            nh.x = sigm(zox) * tanh_f(nc.x);
            nh.y = sigm(zoy) * tanh_f(nc.y);
            c0p[p * H_ + j] = nc;
            h0p[p * H_ + j] = nh;
        }
        __syncthreads();

        // ---------- layer 1 GEMM (3-way split-K) ----------
#pragma unroll
        for (int p = 0; p < P_; ++p) { z[0][p] = bias1a; z[1][p] = bias1b; }
        if (sp == 0) {
            gemm_g<H_, 11>(g_Wih1T4, h0p, 0, z, g0);
            gemm_g<H_, 11>(g_Whh1T4, h1p, 0, z, g0);
        } else if (sp == 1) {
            gemm_g<H_, 11>(g_Wih1T4 + 11 * G_, h0p, 11, z, g0);
            gemm_g<H_, 11>(g_Whh1T4 + 11 * G_, h1p, 11, z, g0);
        } else {
            gemm_g<H_, 10>(g_Wih1T4 + 22 * G_, h0p, 22, z, g0);
            gemm_g<H_, 10>(g_Whh1T4 + 22 * G_, h1p, 22, z, g0);
        }
#pragma unroll
        for (int p = 0; p < P_; ++p) {
            zmy[g0 * PST + p] = z[0][p];
            zmy[(g0 + 256) * PST + p] = z[1][p];
        }
        // stage x(t+1) into the other buffer while z settles
        if (t + 1 < T_) {
            for (int i = tid; i < BT * F_; i += NT) {
                int b = i / F_, f = i % F_;
                float v = (b < nb)
                    ? x[((size_t)(b_base + b) * T_ + (t + 1)) * F_ + f]
                    : 0.0f;
                ((float*)xb[cur ^ 1])[(b >> 1) * F_ * 2 + f * 2 + (b & 1)] = v;
            }
        }
        __syncthreads();

        // ---------- layer 1 gate update ----------
        for (int i = tid; i < P_ * H_; i += NT) {
            int p = i >> 7, j = i & (H_ - 1);
            float zix, ziy, zfx, zfy, zgx, zgy, zox, zoy;
            {
                float2 a0 = u2f(zbu0[(j      ) * PST + p]);
                float2 a1 = u2f(zbu1[(j      ) * PST + p]);
                float2 a2 = u2f(zbu2[(j      ) * PST + p]);
                zix = a0.x + a1.x + a2.x; ziy = a0.y + a1.y + a2.y;
            }
            {
                float2 a0 = u2f(zbu0[(j + 128) * PST + p]);
                float2 a1 = u2f(zbu1[(j + 128) * PST + p]);
                float2 a2 = u2f(zbu2[(j + 128) * PST + p]);
                zfx = a0.x + a1.x + a2.x; zfy = a0.y + a1.y + a2.y;
            }
            {
                float2 a0 = u2f(zbu0[(j + 256) * PST + p]);
                float2 a1 = u2f(zbu1[(j + 256) * PST + p]);
                float2 a2 = u2f(zbu2[(j + 256) * PST + p]);
                zgx = a0.x + a1.x + a2.x; zgy = a0.y + a1.y + a2.y;
            }
            {
                float2 a0 = u2f(zbu0[(j + 384) * PST + p]);
                float2 a1 = u2f(zbu1[(j + 384) * PST + p]);
                float2 a2 = u2f(zbu2[(j + 384) * PST + p]);
                zox = a0.x + a1.x + a2.x; zoy = a0.y + a1.y + a2.y;
            }
            float2 c = c1p[p * H_ + j];
            float2 nc, nh;
            nc.x = sigm(zfx) * c.x + sigm(zix) * tanh_f(zgx);
            nc.y = sigm(zfy) * c.y + sigm(ziy) * tanh_f(zgy);
            nh.x = sigm(zox) * tanh_f(nc.x);
            nh.y = sigm(zoy) * tanh_f(nc.y);
            c1p[p * H_ + j] = nc;
            h1p[p * H_ + j] = nh;
        }
        __syncthreads();
        cur ^= 1;
    }

    // FC head
    if (tid < nb) {
        float s = bfc[0];
#pragma unroll
        for (int k = 0; k < H_; ++k) {
            float2 hv = h1p[(tid >> 1) * H_ + k];
            float h = (tid & 1) ? hv.y : hv.x;
            s = fmaf(h, Wfc[k], s);
        }
        out[b_base + tid] = s;
    }
}

extern "C" void kernel_launch(void* const* d_in, const int* in_sizes, int n_in,
                              void* d_out, int out_size) {
    const float* x    = (const float*)d_in[0];
    const float* Wih0 = (const float*)d_in[1];
    const float* Whh0 = (const float*)d_in[2];
    const float* b0   = (const float*)d_in[3];
    const float* Wih1 = (const float*)d_in[4];
    const float* Whh1 = (const float*)d_in[5];
    const float* b1   = (const float*)d_in[6];
    const float* Wfc  = (const float*)d_in[7];
    const float* bfc  = (const float*)d_in[8];
    float* out = (float*)d_out;
    (void)in_sizes; (void)n_in; (void)out_size;

    prep<<<(G_ * (H_ / 4)) / 256, 256>>>(Wih0, Whh0, Wih1, Whh1);

    const int smem_bytes =
        (F_ / 4 + CWHH) * G_ * (int)sizeof(float4) +   // weight caches
        4 * P_ * H_ * (int)sizeof(float2) +            // h/c
        3 * G_ * PST * (int)sizeof(ull) +              // split-K zbufs
        2 * P_ * F_ * (int)sizeof(float2);             // x double buffer
    cudaFuncSetAttribute(lstm_persistent,
                         cudaFuncAttributeMaxDynamicSharedMemorySize,
                         smem_bytes);

    lstm_persistent<<<(B_ + BT - 1) / BT, NT, smem_bytes>>>(
        x, b0, b1, Wfc, bfc, out);
}

// round 11
// speedup vs baseline: 1.3815x; 1.0324x over previous
#include <cuda_runtime.h>
#include <math.h>

// Problem constants
#define B_  2048
#define T_  512
#define F_  32
#define H_  128
#define BT  14       // batch rows per CTA -> 147 CTAs = one wave on 148 SMs
#define P_  7        // batch pairs per CTA
#define NT  512      // (half: pairs 0-3 / 4-6) x (ksplit: lo/hi K) x 128 j
#define PST 9        // zbuf stride in ull per gate row
#define CWHH 5       // Whh0 kg-rows cached in SMEM (of 32)

typedef unsigned long long ull;

// Weights laid out [kg][gt][j] float4 (4 consecutive k per load):
// index = (kg*4 + gt)*128 + j ; gate = gt*128 + j ; k = 4*kg.
// Lanes (consecutive j) are fully coalesced. +2 kg rows pad for prefetch.
__device__ float4 g_Wih0p[(8 + 2) * 512];
__device__ float4 g_Whh0p[(32 + 2) * 512];
__device__ float4 g_Wih1p[(32 + 2) * 512];
__device__ float4 g_Whh1p[(32 + 2) * 512];

__global__ void prep(const float* __restrict__ Wih0,
                     const float* __restrict__ Whh0,
                     const float* __restrict__ Wih1,
                     const float* __restrict__ Whh1) {
    int idx = blockIdx.x * blockDim.x + threadIdx.x;  // 0..16383
    int j = idx & 127, gt = (idx >> 7) & 3, kg = idx >> 9;
    int gate = gt * 128 + j;
    g_Whh0p[idx] = *(const float4*)(Whh0 + gate * 128 + 4 * kg);
    g_Wih1p[idx] = *(const float4*)(Wih1 + gate * 128 + 4 * kg);
    g_Whh1p[idx] = *(const float4*)(Whh1 + gate * 128 + 4 * kg);
    if (kg < 8)
        g_Wih0p[idx] = *(const float4*)(Wih0 + gate * 32 + 4 * kg);
}

__device__ __forceinline__ ull ffma2(ull a, ull b, ull c) {
    ull d;
    asm("fma.rn.f32x2 %0, %1, %2, %3;" : "=l"(d) : "l"(a), "l"(b), "l"(c));
    return d;
}
__device__ __forceinline__ ull dup2(float w) {
    ull d;
    asm("mov.b64 %0, {%1, %1};" : "=l"(d) : "f"(w));
    return d;
}
__device__ __forceinline__ float2 u2f(ull v) {
    float2 r;
    asm("mov.b64 {%0, %1}, %2;" : "=f"(r.x), "=f"(r.y) : "l"(v));
    return r;
}
__device__ __forceinline__ float sigm(float x) {
    return 1.0f / (1.0f + __expf(-x));
}
__device__ __forceinline__ float tanh_f(float x) {
    float e = __expf(-2.0f * fabsf(x));
    float t = (1.0f - e) / (1.0f + e);
    return x >= 0.0f ? t : -t;
}

// 2 k-values, 4 gates, NP pairs. kp = 16B index into each pair's h row.
template <int KDIM, int NP>
__device__ __forceinline__ void k2body(float2 w0, float2 w1, float2 w2, float2 w3,
                                       const float2* __restrict__ hp,
                                       ull z[4][NP], int kp) {
    ull d00 = dup2(w0.x), d01 = dup2(w0.y);
    ull d10 = dup2(w1.x), d11 = dup2(w1.y);
    ull d20 = dup2(w2.x), d21 = dup2(w2.y);
    ull d30 = dup2(w3.x), d31 = dup2(w3.y);
#pragma unroll
    for (int p = 0; p < NP; ++p) {
        ulonglong2 v = ((const ulonglong2*)(hp + p * KDIM))[kp];
        z[0][p] = ffma2(v.y, d01, ffma2(v.x, d00, z[0][p]));
        z[1][p] = ffma2(v.y, d11, ffma2(v.x, d10, z[1][p]));
        z[2][p] = ffma2(v.y, d21, ffma2(v.x, d20, z[2][p]));
        z[3][p] = ffma2(v.y, d31, ffma2(v.x, d30, z[3][p]));
    }
}

// full k-group (4 k) from a float4-per-gate weight vector
template <int KDIM, int NP>
__device__ __forceinline__ void kbody4(const float4 w[4],
                                       const float2* __restrict__ hp,
                                       ull z[4][NP], int kidx) {
    k2body<KDIM, NP>(make_float2(w[0].x, w[0].y), make_float2(w[1].x, w[1].y),
                     make_float2(w[2].x, w[2].y), make_float2(w[3].x, w[3].y),
                     hp, z, 2 * kidx);
    k2body<KDIM, NP>(make_float2(w[0].z, w[0].w), make_float2(w[1].z, w[1].w),
                     make_float2(w[2].z, w[2].w), make_float2(w[3].z, w[3].w),
                     hp, z, 2 * kidx + 1);
}

// Streamed panel: Wt already offset to (kbase row, gt=0, j). Row stride 512
// float4; gt stride 128. Distance-2 rolling prefetch (+2 pad rows exist).
template <int KDIM, int KG, int NP>
__device__ __forceinline__ void panel_g4(const float4* __restrict__ Wt,
                                         const float2* __restrict__ hp,
                                         int kbase, ull z[4][NP]) {
    float4 w0[4], w1[4];
#pragma unroll
    for (int gt = 0; gt < 4; ++gt) { w0[gt] = Wt[gt * 128]; w1[gt] = Wt[512 + gt * 128]; }
#pragma unroll 1
    for (int kg = 0; kg < KG; ++kg) {
        float4 wn[4];
#pragma unroll
        for (int gt = 0; gt < 4; ++gt) wn[gt] = Wt[(size_t)(kg + 2) * 512 + gt * 128];
        kbody4<KDIM, NP>(w0, hp, z, kbase + kg);
#pragma unroll
        for (int gt = 0; gt < 4; ++gt) { w0[gt] = w1[gt]; w1[gt] = wn[gt]; }
    }
}

// Cached panel: Ws already offset to j within the cache.
template <int KDIM, int KG, int NP>
__device__ __forceinline__ void panel_s4(const float4* __restrict__ Ws,
                                         const float2* __restrict__ hp,
                                         int kbase, ull z[4][NP]) {
#pragma unroll 1
    for (int kg = 0; kg < KG; ++kg) {
        float4 w[4];
#pragma unroll
        for (int gt = 0; gt < 4; ++gt) w[gt] = Ws[kg * 512 + gt * 128];
        kbody4<KDIM, NP>(w, hp, z, kbase + kg);
    }
}

template <int NP>
__device__ __forceinline__ void l0_gemm(const float4* __restrict__ sWih0,
                                        const float4* __restrict__ sWhh0,
                                        const float2* __restrict__ xi,
                                        const float2* __restrict__ h0,
                                        ull z[4][NP], int j, int ks) {
    if (ks == 0) {
        panel_s4<F_, 4, NP>(sWih0 + j, xi, 0, z);
        panel_s4<H_, CWHH, NP>(sWhh0 + j, h0, 0, z);
        panel_g4<H_, 16 - CWHH, NP>(g_Whh0p + CWHH * 512 + j, h0, CWHH, z);
    } else {
        panel_s4<F_, 4, NP>(sWih0 + 4 * 512 + j, xi, 4, z);
        panel_g4<H_, 16, NP>(g_Whh0p + 16 * 512 + j, h0, 16, z);
    }
}

template <int NP>
__device__ __forceinline__ void l1_gemm(const float2* __restrict__ h0,
                                        const float2* __restrict__ h1,
                                        ull z[4][NP], int j, int ks) {
    if (ks == 0) {
        panel_g4<H_, 16, NP>(g_Wih1p + j, h0, 0, z);
        panel_g4<H_, 16, NP>(g_Whh1p + j, h1, 0, z);
    } else {
        panel_g4<H_, 16, NP>(g_Wih1p + 16 * 512 + j, h0, 16, z);
        panel_g4<H_, 16, NP>(g_Whh1p + 16 * 512 + j, h1, 16, z);
    }
}

template <int NP>
__device__ __forceinline__ void store_z(ull z[4][NP], ull* __restrict__ zmy,
                                        int j, int pofs) {
#pragma unroll
    for (int gt = 0; gt < 4; ++gt)
#pragma unroll
        for (int p = 0; p < NP; ++p)
            zmy[(gt * 128 + j) * PST + pofs + p] = z[gt][p];
}

extern __shared__ float4 smem4[];

__global__ void __launch_bounds__(NT, 1)
lstm_persistent(const float* __restrict__ x,
                const float* __restrict__ b0,
                const float* __restrict__ b1,
                const float* __restrict__ Wfc,
                const float* __restrict__ bfc,
                float* __restrict__ out) {
    // SMEM: [Wih0 8 rows][Whh0 CWHH rows][sb0,sb1][h0,c0,h1,c1][zbuf x2][x x2]
    float4* sWih0 = smem4;                          // 8*512 f4 = 64KB
    float4* sWhh0 = smem4 + 8 * 512;                // CWHH*512 f4
    float* sb0 = (float*)(smem4 + (8 + CWHH) * 512);  // 512 f
    float* sb1 = sb0 + 512;                           // 512 f
    float2* hbase = (float2*)(sb1 + 512);
    float2* h0p = hbase;                 // P_*H_
    float2* c0p = h0p + P_ * H_;
    float2* h1p = c0p + P_ * H_;
    float2* c1p = h1p + P_ * H_;
    ull* zbu0 = (ull*)(c1p + P_ * H_);   // 512*PST per ksplit
    ull* zbu1 = zbu0 + 512 * PST;
    float2* xb[2] = { (float2*)(zbu1 + 512 * PST),
                      (float2*)(zbu1 + 512 * PST) + P_ * F_ };

    const int tid = threadIdx.x;
    const int j = tid & 127;             // output index
    const int ks = (tid >> 7) & 1;       // k-split
    const int half = tid >> 8;           // batch-pair half
    const int pofs = half ? 4 : 0;
    const int b_base = blockIdx.x * BT;
    const int nb = min(BT, B_ - b_base);
    ull* zmy = ks ? zbu1 : zbu0;

    // fill weight caches + biases (once per launch)
    for (int i = tid; i < 8 * 512; i += NT) sWih0[i] = g_Wih0p[i];
    for (int i = tid; i < CWHH * 512; i += NT) sWhh0[i] = g_Whh0p[i];
    if (tid < 512) { sb0[tid] = b0[tid]; sb1[tid] = b1[tid]; }
    // zero h/c
    for (int i = tid; i < 4 * P_ * H_; i += NT) hbase[i] = make_float2(0.f, 0.f);
    // stage x(t=0)
    for (int i = tid; i < BT * F_; i += NT) {
        int b = i / F_, f = i % F_;
        float v = (b < nb) ? x[((size_t)(b_base + b) * T_) * F_ + f] : 0.0f;
        ((float*)xb[0])[(b >> 1) * F_ * 2 + f * 2 + (b & 1)] = v;
    }
    __syncthreads();

    int cur = 0;
    for (int t = 0; t < T_; ++t) {
        // ---------- layer 0 GEMM ----------
        if (half == 0) {
            ull z[4][4];
#pragma unroll
            for (int gt = 0; gt < 4; ++gt)
#pragma unroll
                for (int p = 0; p < 4; ++p) z[gt][p] = 0ull;
            l0_gemm<4>(sWih0, sWhh0, xb[cur], h0p, z, j, ks);
            store_z<4>(z, zmy, j, 0);
        } else {
            ull z[4][3];
#pragma unroll
            for (int gt = 0; gt < 4; ++gt)
#pragma unroll
                for (int p = 0; p < 3; ++p) z[gt][p] = 0ull;
            l0_gemm<3>(sWih0, sWhh0, xb[cur] + 4 * F_, h0p + 4 * H_, z, j, ks);
            store_z<3>(z, zmy, j, 4);
        }
        __syncthreads();

        // ---------- layer 0 gate update ----------
        for (int i = tid; i < P_ * H_; i += NT) {
            int p = i >> 7, j2 = i & 127;
            float2 vA, vB;
            vA = u2f(zbu0[(j2      ) * PST + p]); vB = u2f(zbu1[(j2      ) * PST + p]);
            float zix = vA.x + vB.x + sb0[j2],        ziy = vA.y + vB.y + sb0[j2];
            vA = u2f(zbu0[(j2 + 128) * PST + p]); vB = u2f(zbu1[(j2 + 128) * PST + p]);
            float zfx = vA.x + vB.x + sb0[j2 + 128],  zfy = vA.y + vB.y + sb0[j2 + 128];
            vA = u2f(zbu0[(j2 + 256) * PST + p]); vB = u2f(zbu1[(j2 + 256) * PST + p]);
            float zgx = vA.x + vB.x + sb0[j2 + 256],  zgy = vA.y + vB.y + sb0[j2 + 256];
            vA = u2f(zbu0[(j2 + 384) * PST + p]); vB = u2f(zbu1[(j2 + 384) * PST + p]);
            float zox = vA.x + vB.x + sb0[j2 + 384],  zoy = vA.y + vB.y + sb0[j2 + 384];
            float2 c = c0p[p * H_ + j2];
            float2 nc, nh;
            nc.x = sigm(zfx) * c.x + sigm(zix) * tanh_f(zgx);
            nc.y = sigm(zfy) * c.y + sigm(ziy) * tanh_f(zgy);
            nh.x = sigm(zox) * tanh_f(nc.x);
            nh.y = sigm(zoy) * tanh_f(nc.y);
            c0p[p * H_ + j2] = nc;
            h0p[p * H_ + j2] = nh;
        }
        __syncthreads();

        // ---------- layer 1 GEMM ----------
        if (half == 0) {
            ull z[4][4];
#pragma unroll
            for (int gt = 0; gt < 4; ++gt)
#pragma unroll
                for (int p = 0; p < 4; ++p) z[gt][p] = 0ull;
            l1_gemm<4>(h0p, h1p, z, j, ks);
            store_z<4>(z, zmy, j, 0);
        } else {
            ull z[4][3];
#pragma unroll
            for (int gt = 0; gt < 4; ++gt)
#pragma unroll
                for (int p = 0; p < 3; ++p) z[gt][p] = 0ull;
            l1_gemm<3>(h0p + 4 * H_, h1p + 4 * H_, z, j, ks);
            store_z<3>(z, zmy, j, 4);
        }
        // stage x(t+1) into the other buffer
        if (t + 1 < T_) {
            for (int i = tid; i < BT * F_; i += NT) {
                int b = i / F_, f = i % F_;
                float v = (b < nb)
                    ? x[((size_t)(b_base + b) * T_ + (t + 1)) * F_ + f]
                    : 0.0f;
                ((float*)xb[cur ^ 1])[(b >> 1) * F_ * 2 + f * 2 + (b & 1)] = v;
            }
        }
        __syncthreads();

        // ---------- layer 1 gate update ----------
        for (int i = tid; i < P_ * H_; i += NT) {
            int p = i >> 7, j2 = i & 127;
            float2 vA, vB;
            vA = u2f(zbu0[(j2      ) * PST + p]); vB = u2f(zbu1[(j2      ) * PST + p]);
            float zix = vA.x + vB.x + sb1[j2],        ziy = vA.y + vB.y + sb1[j2];
            vA = u2f(zbu0[(j2 + 128) * PST + p]); vB = u2f(zbu1[(j2 + 128) * PST + p]);
            float zfx = vA.x + vB.x + sb1[j2 + 128],  zfy = vA.y + vB.y + sb1[j2 + 128];
            vA = u2f(zbu0[(j2 + 256) * PST + p]); vB = u2f(zbu1[(j2 + 256) * PST + p]);
            float zgx = vA.x + vB.x + sb1[j2 + 256],  zgy = vA.y + vB.y + sb1[j2 + 256];
            vA = u2f(zbu0[(j2 + 384) * PST + p]); vB = u2f(zbu1[(j2 + 384) * PST + p]);
            float zox = vA.x + vB.x + sb1[j2 + 384],  zoy = vA.y + vB.y + sb1[j2 + 384];
            float2 c = c1p[p * H_ + j2];
            float2 nc, nh;
            nc.x = sigm(zfx) * c.x + sigm(zix) * tanh_f(zgx);
            nc.y = sigm(zfy) * c.y + sigm(ziy) * tanh_f(zgy);
            nh.x = sigm(zox) * tanh_f(nc.x);
            nh.y = sigm(zoy) * tanh_f(nc.y);
            c1p[p * H_ + j2] = nc;
            h1p[p * H_ + j2] = nh;
        }
        __syncthreads();
        cur ^= 1;
    }

    // FC head
    if (tid < nb) {
        float s = bfc[0];
#pragma unroll
        for (int k = 0; k < H_; ++k) {
            float2 hv = h1p[(tid >> 1) * H_ + k];
            float h = (tid & 1) ? hv.y : hv.x;
            s = fmaf(h, Wfc[k], s);
        }
        out[b_base + tid] = s;
    }
}

extern "C" void kernel_launch(void* const* d_in, const int* in_sizes, int n_in,
                              void* d_out, int out_size) {
    const float* x    = (const float*)d_in[0];
    const float* Wih0 = (const float*)d_in[1];
    const float* Whh0 = (const float*)d_in[2];
    const float* b0   = (const float*)d_in[3];
    const float* Wih1 = (const float*)d_in[4];
    const float* Whh1 = (const float*)d_in[5];
    const float* b1   = (const float*)d_in[6];
    const float* Wfc  = (const float*)d_in[7];
    const float* bfc  = (const float*)d_in[8];
    float* out = (float*)d_out;
    (void)in_sizes; (void)n_in; (void)out_size;

    prep<<<64, 256>>>(Wih0, Whh0, Wih1, Whh1);

    const int smem_bytes =
        (8 + CWHH) * 512 * (int)sizeof(float4) +   // weight caches
        2 * 512 * (int)sizeof(float) +             // biases
        4 * P_ * H_ * (int)sizeof(float2) +        // h/c
        2 * 512 * PST * (int)sizeof(ull) +         // split-K zbufs
        2 * P_ * F_ * (int)sizeof(float2);         // x double buffer
    cudaFuncSetAttribute(lstm_persistent,
                         cudaFuncAttributeMaxDynamicSharedMemorySize,
                         smem_bytes);

    lstm_persistent<<<(B_ + BT - 1) / BT, NT, smem_bytes>>>(
        x, b0, b1, Wfc, bfc, out);
}